// round 1
// baseline (speedup 1.0000x reference)
#include <cuda_runtime.h>

// ---------------------------------------------------------------------------
// EdgeConv (mlp_layer=0, aggregate=max), restructured:
//   t      = feat @ theta_w                      [N, 64]
//   base   = t + feat @ phi_w + theta_b + phi_b  [N, 64]   (written to d_out)
//   out[v] = base[v] - min_k t[nbr[v,k]]         (per-feature min)
// ---------------------------------------------------------------------------

#define F_DIM 64
#define N_MAX 120000

__device__ float g_t[(size_t)N_MAX * F_DIM];   // scratch for t
__device__ int   g_idx_is64;                   // 1 if nbr_idx is int64

// ---------------------------------------------------------------------------
// Kernel 0: detect index dtype. int64 little-endian indices < 2^31 have all
// odd 32-bit words == 0; random int32 indices make that virtually impossible.
// ---------------------------------------------------------------------------
__global__ void detect_idx_kernel(const unsigned int* __restrict__ raw, int n_elems)
{
    int pairs = 16;
    if (n_elems < 32) pairs = n_elems / 2;
    int is64 = 1;
    for (int i = 0; i < pairs; i++) {
        if (raw[2 * i + 1] != 0u) { is64 = 0; break; }
    }
    g_idx_is64 = is64;
}

// ---------------------------------------------------------------------------
// Kernel 1: fused SGEMM  C = feat @ [theta_w | phi_w]   (M=N nodes, N=128, K=64)
// BM=128 rows/block, 256 threads, 8x(4+4) register tile per thread.
// Each thread owns output features tx*4..tx*4+3 for BOTH theta and phi halves,
// so base = accT + accP combines locally.
// ---------------------------------------------------------------------------
#define BM 128
#define BK 32
#define TM 8
#define TN 4

__global__ __launch_bounds__(256)
void fused_gemm_kernel(const float* __restrict__ feat,
                       const float* __restrict__ theta_w,
                       const float* __restrict__ theta_b,
                       const float* __restrict__ phi_w,
                       const float* __restrict__ phi_b,
                       float* __restrict__ out,
                       int n)
{
    __shared__ float sA[BK][BM + 1];   // [k][row]  (transposed feat tile)
    __shared__ float sB[BK][128];      // [k][c]    c<64: theta_w, c>=64: phi_w

    const int tid = threadIdx.x;
    const int tx  = tid & 15;    // 0..15 -> feature group (4 feats)
    const int ty  = tid >> 4;    // 0..15 -> row group (8 rows)
    const int rb  = blockIdx.x * BM;

    float accT[TM][TN], accP[TM][TN];
#pragma unroll
    for (int i = 0; i < TM; i++)
#pragma unroll
        for (int j = 0; j < TN; j++) { accT[i][j] = 0.f; accP[i][j] = 0.f; }

    for (int kk = 0; kk < F_DIM; kk += BK) {
        // --- load A tile (transposed): sA[k][row] = feat[row][kk+k] ---
        {
            const int c  = tid & 31;   // k within chunk
            const int r0 = tid >> 5;   // 0..7
#pragma unroll
            for (int p = 0; p < 16; p++) {
                int r   = r0 + p * 8;
                int row = rb + r;
                sA[c][r] = (row < n) ? feat[(long long)row * F_DIM + kk + c] : 0.f;
            }
        }
        // --- load B tile: sB[k][c] ---
        {
#pragma unroll
            for (int p = 0; p < 16; p++) {
                int idx = tid + p * 256;          // 0..4095
                int k   = idx >> 7;               // 0..31
                int c   = idx & 127;              // 0..127
                float v = (c < 64) ? theta_w[(kk + k) * F_DIM + c]
                                   : phi_w[(kk + k) * F_DIM + (c - 64)];
                sB[k][c] = v;
            }
        }
        __syncthreads();

#pragma unroll
        for (int k = 0; k < BK; k++) {
            float a[TM];
#pragma unroll
            for (int i = 0; i < TM; i++) a[i] = sA[k][ty * TM + i];
            float4 bT = *(const float4*)&sB[k][tx * 4];
            float4 bP = *(const float4*)&sB[k][64 + tx * 4];
#pragma unroll
            for (int i = 0; i < TM; i++) {
                accT[i][0] += a[i] * bT.x;  accT[i][1] += a[i] * bT.y;
                accT[i][2] += a[i] * bT.z;  accT[i][3] += a[i] * bT.w;
                accP[i][0] += a[i] * bP.x;  accP[i][1] += a[i] * bP.y;
                accP[i][2] += a[i] * bP.z;  accP[i][3] += a[i] * bP.w;
            }
        }
        __syncthreads();
    }

    // --- epilogue: write t and base ---
    float bias[TN];
#pragma unroll
    for (int j = 0; j < TN; j++) bias[j] = theta_b[tx * 4 + j] + phi_b[tx * 4 + j];

#pragma unroll
    for (int i = 0; i < TM; i++) {
        int row = rb + ty * TM + i;
        if (row < n) {
            long long off = (long long)row * F_DIM + tx * 4;
            float4 tv = make_float4(accT[i][0], accT[i][1], accT[i][2], accT[i][3]);
            *(float4*)&g_t[off] = tv;
            float4 bv = make_float4(accT[i][0] + accP[i][0] + bias[0],
                                    accT[i][1] + accP[i][1] + bias[1],
                                    accT[i][2] + accP[i][2] + bias[2],
                                    accT[i][3] + accP[i][3] + bias[3]);
            *(float4*)&out[off] = bv;
        }
    }
}

// ---------------------------------------------------------------------------
// Kernel 2: gather-min.  One warp per node; lane owns 2 features (float2).
// Indices preloaded into registers -> 16 independent gathers (MLP=16).
// ---------------------------------------------------------------------------
__global__ __launch_bounds__(256)
void gather_min_kernel(const void* __restrict__ nbr_raw,
                       float* __restrict__ out,
                       int n, int K)
{
    int w    = (int)((blockIdx.x * (long long)blockDim.x + threadIdx.x) >> 5);
    int lane = threadIdx.x & 31;
    if (w >= n) return;

    const float2* t2 = (const float2*)g_t;
    const bool is64 = (g_idx_is64 != 0);

    float2 m = make_float2(3.402823466e+38f, 3.402823466e+38f);

    if (K == 16) {
        long long u[16];
        if (is64) {
            const long long* nb = (const long long*)nbr_raw + (long long)w * 16;
#pragma unroll
            for (int j = 0; j < 16; j++) u[j] = nb[j];
        } else {
            const int* nb = (const int*)nbr_raw + (long long)w * 16;
#pragma unroll
            for (int j = 0; j < 16; j++) u[j] = (long long)nb[j];
        }
#pragma unroll
        for (int j = 0; j < 16; j++) {
            float2 v = __ldg(&t2[u[j] * 32 + lane]);
            m.x = fminf(m.x, v.x);
            m.y = fminf(m.y, v.y);
        }
    } else {
        for (int j = 0; j < K; j++) {
            long long u = is64 ? ((const long long*)nbr_raw)[(long long)w * K + j]
                               : (long long)((const int*)nbr_raw)[(long long)w * K + j];
            float2 v = __ldg(&t2[u * 32 + lane]);
            m.x = fminf(m.x, v.x);
            m.y = fminf(m.y, v.y);
        }
    }

    long long o = (long long)w * 32 + lane;
    float2* out2 = (float2*)out;
    float2 b = out2[o];
    b.x -= m.x;
    b.y -= m.y;
    out2[o] = b;
}

// ---------------------------------------------------------------------------
// Launch
// ---------------------------------------------------------------------------
extern "C" void kernel_launch(void* const* d_in, const int* in_sizes, int n_in,
                              void* d_out, int out_size)
{
    const float* feat    = (const float*)d_in[0];
    const void*  nbr     = d_in[1];
    const float* theta_w = (const float*)d_in[2];
    const float* theta_b = (const float*)d_in[3];
    const float* phi_w   = (const float*)d_in[4];
    const float* phi_b   = (const float*)d_in[5];
    float* out = (float*)d_out;

    const int n = in_sizes[0] / F_DIM;     // number of nodes
    const int K = in_sizes[1] / n;         // neighbors per node (=16)

    detect_idx_kernel<<<1, 1>>>((const unsigned int*)nbr, in_sizes[1]);

    int g1 = (n + BM - 1) / BM;
    fused_gemm_kernel<<<g1, 256>>>(feat, theta_w, theta_b, phi_w, phi_b, out, n);

    long long total_threads = (long long)n * 32;
    int g2 = (int)((total_threads + 255) / 256);
    gather_min_kernel<<<g2, 256>>>(nbr, out, n, K);
}